// round 8
// baseline (speedup 1.0000x reference)
#include <cuda_runtime.h>
#include <cstdint>

#define NMAX   500000
#define HBITS  21
#define HSIZE  (1u << HBITS)
#define HMASK  (HSIZE - 1u)
#define EMPTYK 0xFFFFFFFFu
#define TPM    256
#define PPW    4      // points per warp iteration in k_mlp

typedef unsigned long long ull;

// ---------------- device scratch ----------------
__device__ uint32_t g_keys[3][HSIZE];
__device__ int      g_vals[3][HSIZE];
__device__ int      g_counter[3];
__device__ int      g_pt2vox[3][NMAX];
__device__ float    g_sums[3][NMAX * 64];
__device__ int      g_counts[3][NMAX];
__device__ int2     g_pidx[3][NMAX];     // (voxel id, 1/count as float bits)
__device__ float    g_ms[3][NMAX * 64];

__device__ __forceinline__ uint32_t hash32(uint32_t x) {
    x ^= x >> 16; x *= 0x85ebca6bu;
    x ^= x >> 13; x *= 0xc2b2ae35u;
    x ^= x >> 16;
    return x;
}

__device__ __forceinline__ ull fma2(ull a, ull b, ull c) {
    ull d;
    asm("fma.rn.f32x2 %0, %1, %2, %3;" : "=l"(d) : "l"(a), "l"(b), "l"(c));
    return d;
}
__device__ __forceinline__ float2 unpack2(ull v) {
    float2 r;
    asm("mov.b64 {%0, %1}, %2;" : "=f"(r.x), "=f"(r.y) : "l"(v));
    return r;
}

// ---------------- K1: clear hash tables + counts (NOT sums) ----------------
__global__ void k_clear1(int n) {
    int tid = blockIdx.x * blockDim.x + threadIdx.x;
    int stride = gridDim.x * blockDim.x;
    for (int i = tid; i < (int)HSIZE; i += stride) {
        g_keys[0][i] = EMPTYK; g_keys[1][i] = EMPTYK; g_keys[2][i] = EMPTYK;
        g_vals[0][i] = -1;     g_vals[1][i] = -1;     g_vals[2][i] = -1;
    }
    for (int i = tid; i < n; i += stride) {
        g_counts[0][i] = 0; g_counts[1][i] = 0; g_counts[2][i] = 0;
    }
    if (tid == 0) { g_counter[0] = 0; g_counter[1] = 0; g_counter[2] = 0; }
}

// ---------------- K2: hash-insert (all scales via blockIdx.y) ----------------
__global__ void k_insert(const int* __restrict__ coords, int n) {
    int i = blockIdx.x * blockDim.x + threadIdx.x;
    if (i >= n) return;
    int si = blockIdx.y;
    int shift = si + 1;
    int4 cd = reinterpret_cast<const int4*>(coords)[i];
    int vx = cd.x >> shift, vy = cd.y >> shift, vz = cd.z >> shift;
    uint32_t key = (uint32_t)((((cd.w * 512) + vx) * 512 + vy) * 512 + vz);
    uint32_t slot = hash32(key) & HMASK;
    int id = -1;
#pragma unroll 1
    while (true) {
        uint32_t old = atomicCAS(&g_keys[si][slot], EMPTYK, key);
        if (old == EMPTYK) {
            id = atomicAdd(&g_counter[si], 1);
            atomicExch(&g_vals[si][slot], id);
            break;
        }
        if (old == key) {
            volatile int* vp = (volatile int*)&g_vals[si][slot];
#pragma unroll 1
            while ((id = *vp) < 0) { __nanosleep(40); }
            break;
        }
        slot = (slot + 1) & HMASK;
    }
    g_pt2vox[si][i] = id;
    atomicAdd(&g_counts[si][id], 1);
}

// ---------------- K2b: zero only the used prefix of g_sums ----------------
__global__ void k_clear_sums() {
    int tid = blockIdx.x * blockDim.x + threadIdx.x;
    int stride = gridDim.x * blockDim.x;
    float4 z = make_float4(0.f, 0.f, 0.f, 0.f);
#pragma unroll
    for (int s = 0; s < 3; s++) {
        int m4 = g_counter[s] * 16;
        float4* s4 = reinterpret_cast<float4*>(&g_sums[s][0]);
        for (int i = tid; i < m4; i += stride) s4[i] = z;
    }
}

// ---------------- K3: per-voxel feature sums (all 3 scales, one feats read) ----------------
__global__ void k_accum(const float* __restrict__ feats, int n) {
    int tid = blockIdx.x * blockDim.x + threadIdx.x;
    if (tid >= n * 16) return;
    int p = tid >> 4, q = tid & 15;
    float4 v = reinterpret_cast<const float4*>(feats)[tid];
#pragma unroll
    for (int si = 0; si < 3; si++) {
        int vid = g_pt2vox[si][p];
        float* dst = &g_sums[si][(size_t)vid * 64 + q * 4];
        asm volatile("red.global.add.v4.f32 [%0], {%1, %2, %3, %4};"
                     :: "l"(dst), "f"(v.x), "f"(v.y), "f"(v.z), "f"(v.w)
                     : "memory");
    }
}

// ---------------- K4: 8-corner probe + exact trilinear argmax + inv ----------------
__device__ __forceinline__ int hlookup(int si, uint32_t key) {
    uint32_t slot = hash32(key) & HMASK;
#pragma unroll 1
    while (true) {
        uint32_t k = g_keys[si][slot];
        if (k == key) return g_vals[si][slot];
        if (k == EMPTYK) return -1;
        slot = (slot + 1) & HMASK;
    }
}

__global__ void k_select(const int* __restrict__ coords, int n) {
    int i = blockIdx.x * blockDim.x + threadIdx.x;
    if (i >= n) return;
    int si = blockIdx.y;
    int shift = si + 1;
    int4 cd = reinterpret_cast<const int4*>(coords)[i];
    int scale = 1 << shift;
    float invs = 1.0f / (float)scale;
    int vx = cd.x >> shift, vy = cd.y >> shift, vz = cd.z >> shift;
    float fx = (float)(cd.x - (vx << shift)) * invs;   // exact binary fractions
    float fy = (float)(cd.y - (vy << shift)) * invs;
    float fz = (float)(cd.z - (vz << shift)) * invs;
    float gx = 1.0f - fx, gy = 1.0f - fy, gz = 1.0f - fz;

    float bestw = -1.0f;
    int bestid = 0;
#pragma unroll
    for (int j = 0; j < 8; j++) {
        int bx = (j >> 2) & 1, by = (j >> 1) & 1, bz = j & 1;
        float w = (bx ? fx : gx) * (by ? fy : gy) * (bz ? fz : gz);  // exact
        uint32_t key = (uint32_t)((((cd.w * 512) + (vx + bx)) * 512 + (vy + by)) * 512 + (vz + bz));
        int id = hlookup(si, key);
        float val = (id >= 0) ? w : 0.0f;
        if (val > bestw) { bestw = val; bestid = id; }  // first-max == jnp.argmax
    }
    // precompute 1/count once per point (same value/rounding the MLP used before)
    float inv = 1.0f / (float)g_counts[si][bestid];
    g_pidx[si][i] = make_int2(bestid, __float_as_int(inv));
}

// ---------------- K5: per-scale residual MLP (warp-independent) ----------------
// R5-winning structure: 8 warps/CTA, 4 CTAs/SM, each warp fully independent,
// 4 points per iteration. Weights k-pair-packed in smem (row stride 66 ull,
// phase conflict-free LDS.128); activations broadcast LDS.128.
#define WPK_ULL   (2 * 32 * 66)                    // 4224 ull = 33792 B
#define ACT_OFF_F (WPK_ULL * 2)                    // float index of act region
#define SMEM_MLP  (WPK_ULL * 8 + 8 * 512 * 4)     // 33792 + 16384 = 50176 B

__global__ __launch_bounds__(TPM, 4) void k_mlp(
    const float* __restrict__ feats,
    const float* __restrict__ W1g, const float* __restrict__ b1g,
    const float* __restrict__ W2g, const float* __restrict__ b2g,
    int n)
{
    extern __shared__ ull smu[];
    float* smf = (float*)smu;
    const int s    = blockIdx.y;
    const int bs   = blockIdx.x;
    const int nb   = gridDim.x;
    const int warp = threadIdx.x >> 5;
    const int lane = threadIdx.x & 31;
    const int c0   = lane * 2;

    // ---- stage + k-pair-pack this scale's weights ----
    for (int j = threadIdx.x; j < 8192; j += TPM) {
        int layer = j >> 12, r = j & 4095;
        int k = r >> 6, c = r & 63;
        float v = (layer ? W2g : W1g)[s * 4096 + r];
        smf[(((layer * 32 + (c >> 1)) * 66) + ((k >> 1) << 1) + (c & 1)) * 2 + (k & 1)] = v;
    }
    const float b1x = b1g[s * 64 + c0], b1y = b1g[s * 64 + c0 + 1];
    const float b2x = b2g[s * 64 + c0], b2y = b2g[s * 64 + c0 + 1];
    __syncthreads();

    const ull* w0b = smu + lane * 66;          // layer-1 weight row for this lane
    const ull* w1b = smu + 2112 + lane * 66;   // layer-2
    float* resw = smf + ACT_OFF_F + warp * 512;    // [4][64]
    float* hw   = resw + 256;                       // [4][64]

    const int tiles = (n + 3) >> 2;

#define GEMV(SRCF, WB) do {                                                    \
    _Pragma("unroll") for (int p = 0; p < 4; p++) { a0[p] = 0ull; a1[p] = 0ull; } \
    _Pragma("unroll")                                                          \
    for (int kc = 0; kc < 16; kc++) {                                          \
        ulonglong2 wA = *(const ulonglong2*)&(WB)[4 * kc];                     \
        ulonglong2 wB_ = *(const ulonglong2*)&(WB)[4 * kc + 2];                \
        _Pragma("unroll")                                                      \
        for (int p = 0; p < 4; p++) {                                          \
            ulonglong2 av = *(const ulonglong2*)&((const ull*)(SRCF))[p * 32 + 2 * kc]; \
            a0[p] = fma2(av.x, wA.x, a0[p]);                                   \
            a1[p] = fma2(av.x, wA.y, a1[p]);                                   \
            a0[p] = fma2(av.y, wB_.x, a0[p]);                                  \
            a1[p] = fma2(av.y, wB_.y, a1[p]);                                  \
        }                                                                      \
    }                                                                          \
} while (0)

    for (int t = bs * 8 + warp; t < tiles; t += nb * 8) {
        const int i0 = t * 4;
        float2 pf[4];

        // ---- gather voxel mean + residual (one-level gather: idx/inv packed) ----
#pragma unroll
        for (int p = 0; p < 4; p++) {
            int i = i0 + p; if (i >= n) i = n - 1;
            int2 pi = g_pidx[s][i];
            float inv = __int_as_float(pi.y);
            float2 sv = *(const float2*)&g_sums[s][(size_t)pi.x * 64 + c0];
            float2 f2 = *(const float2*)&feats[(size_t)i * 64 + c0];
            pf[p] = f2;
            *(float2*)&resw[p * 64 + c0] = make_float2(f2.x - sv.x * inv,
                                                       f2.y - sv.y * inv);
        }
        __syncwarp();

        ull a0[4], a1[4];
        // ---- GEMV1: h = relu(res @ W1 + b1) * feats ----
        GEMV(resw, w0b);
#pragma unroll
        for (int p = 0; p < 4; p++) {
            float2 u0 = unpack2(a0[p]);
            float2 u1 = unpack2(a1[p]);
            float h0 = fmaxf(u0.x + u0.y + b1x, 0.0f) * pf[p].x;
            float h1 = fmaxf(u1.x + u1.y + b1y, 0.0f) * pf[p].y;
            *(float2*)&hw[p * 64 + c0] = make_float2(h0, h1);
        }
        __syncwarp();

        // ---- GEMV2: ms = relu(h @ W2 + b2) ----
        GEMV(hw, w1b);
#pragma unroll
        for (int p = 0; p < 4; p++) {
            if (i0 + p < n) {
                float2 u0 = unpack2(a0[p]);
                float2 u1 = unpack2(a1[p]);
                float m0 = fmaxf(u0.x + u0.y + b2x, 0.0f);
                float m1 = fmaxf(u1.x + u1.y + b2y, 0.0f);
                *(float2*)&g_ms[s][(size_t)(i0 + p) * 64 + c0] = make_float2(m0, m1);
            }
        }
        __syncwarp();
    }
#undef GEMV
}

// ---------------- K6: attention + combine (streaming) ----------------
__global__ __launch_bounds__(256) void k_att(
    const float* __restrict__ Wag, const float* __restrict__ bag,
    float* __restrict__ out, int n)
{
    int warp = threadIdx.x >> 5, lane = threadIdx.x & 31;
    int i = blockIdx.x * 8 + warp;
    if (i >= n) return;
    int c0 = lane * 2;

    float2 m0 = *(const float2*)&g_ms[0][(size_t)i * 64 + c0];
    float2 m1 = *(const float2*)&g_ms[1][(size_t)i * 64 + c0];
    float2 m2 = *(const float2*)&g_ms[2][(size_t)i * 64 + c0];
    float ssx = m0.x + m1.x + m2.x;
    float ssy = m0.y + m1.y + m2.y;

    float2 wa0 = *(const float2*)&Wag[c0];
    float2 wa1 = *(const float2*)&Wag[64 + c0];
    float2 wa2 = *(const float2*)&Wag[128 + c0];
    float p0 = ssx * wa0.x + ssy * wa0.y;
    float p1 = ssx * wa1.x + ssy * wa1.y;
    float p2 = ssx * wa2.x + ssy * wa2.y;
#pragma unroll
    for (int off = 16; off; off >>= 1) {
        p0 += __shfl_xor_sync(0xffffffffu, p0, off);
        p1 += __shfl_xor_sync(0xffffffffu, p1, off);
        p2 += __shfl_xor_sync(0xffffffffu, p2, off);
    }
    float a0 = 1.0f / (1.0f + expf(-(p0 + bag[0])));
    float a1 = 1.0f / (1.0f + expf(-(p1 + bag[1])));
    float a2 = 1.0f / (1.0f + expf(-(p2 + bag[2])));

    float2 o;
    o.x = m0.x * a0 + m1.x * a1 + m2.x * a2;
    o.y = m0.y * a0 + m1.y * a1 + m2.y * a2;
    *(float2*)&out[(size_t)i * 64 + c0] = o;
}

// ---------------- host launcher ----------------
extern "C" void kernel_launch(void* const* d_in, const int* in_sizes, int n_in,
                              void* d_out, int out_size) {
    const float* feats = (const float*)d_in[0];
    const int*   coords = (const int*)d_in[1];
    const float* W1 = (const float*)d_in[2];
    const float* b1 = (const float*)d_in[3];
    const float* W2 = (const float*)d_in[4];
    const float* b2 = (const float*)d_in[5];
    const float* Wa = (const float*)d_in[6];
    const float* ba = (const float*)d_in[7];
    float* out = (float*)d_out;

    int n = in_sizes[1] / 4;   // coords is (N,4) int32
    if (n > NMAX) n = NMAX;

    k_clear1<<<2048, 256>>>(n);
    dim3 gi((n + 255) / 256, 3);
    k_insert<<<gi, 256>>>(coords, n);
    k_clear_sums<<<2048, 256>>>();
    k_accum<<<(n * 16 + 255) / 256, 256>>>(feats, n);
    k_select<<<gi, 256>>>(coords, n);

    int sms = 148;
    cudaDeviceGetAttribute(&sms, cudaDevAttrMultiProcessorCount, 0);
    cudaFuncSetAttribute(k_mlp, cudaFuncAttributeMaxDynamicSharedMemorySize, SMEM_MLP);
    dim3 gm(sms * 4, 3);   // 4 CTAs/SM resident, persistent over tiles
    k_mlp<<<gm, TPM, SMEM_MLP>>>(feats, W1, b1, W2, b2, n);

    k_att<<<(n + 7) / 8, 256>>>(Wa, ba, out, n);
}

// round 9
// speedup vs baseline: 1.2632x; 1.2632x over previous
#include <cuda_runtime.h>
#include <cstdint>

#define NMAX   500000
#define HBITS  21
#define HSIZE  (1u << HBITS)
#define HMASK  (HSIZE - 1u)
#define EMPTYK 0xFFFFFFFFu
#define TPM    256

typedef unsigned long long ull;

// ---------------- device scratch ----------------
__device__ uint32_t g_keys[3][HSIZE];
__device__ int      g_vals[3][HSIZE];
__device__ int      g_counter[3];
__device__ int      g_pt2vox[3][NMAX];
__device__ float    g_sums[3][NMAX * 64];
__device__ int      g_counts[3][NMAX];
__device__ int      g_ptidx[3][NMAX];
__device__ float    g_ms[3][NMAX * 64];

__device__ __forceinline__ uint32_t hash32(uint32_t x) {
    x ^= x >> 16; x *= 0x85ebca6bu;
    x ^= x >> 13; x *= 0xc2b2ae35u;
    x ^= x >> 16;
    return x;
}

__device__ __forceinline__ ull fma2(ull a, ull b, ull c) {
    ull d;
    asm("fma.rn.f32x2 %0, %1, %2, %3;" : "=l"(d) : "l"(a), "l"(b), "l"(c));
    return d;
}
__device__ __forceinline__ float2 unpack2(ull v) {
    float2 r;
    asm("mov.b64 {%0, %1}, %2;" : "=f"(r.x), "=f"(r.y) : "l"(v));
    return r;
}

// ---------------- K1: clear all 3 hash tables + sums/counts ----------------
__global__ void k_clear(int n) {
    int tid = blockIdx.x * blockDim.x + threadIdx.x;
    int stride = gridDim.x * blockDim.x;
    int m4 = n * 16;
    float4 z = make_float4(0.f, 0.f, 0.f, 0.f);
#pragma unroll
    for (int s = 0; s < 3; s++) {
        float4* s4 = reinterpret_cast<float4*>(&g_sums[s][0]);
        for (int i = tid; i < m4; i += stride) s4[i] = z;
    }
    for (int i = tid; i < (int)HSIZE; i += stride) {
        g_keys[0][i] = EMPTYK; g_keys[1][i] = EMPTYK; g_keys[2][i] = EMPTYK;
        g_vals[0][i] = -1;     g_vals[1][i] = -1;     g_vals[2][i] = -1;
    }
    for (int i = tid; i < n; i += stride) {
        g_counts[0][i] = 0; g_counts[1][i] = 0; g_counts[2][i] = 0;
    }
    if (tid == 0) { g_counter[0] = 0; g_counter[1] = 0; g_counter[2] = 0; }
}

// ---------------- K2: hash-insert (all scales via blockIdx.y) ----------------
__global__ void k_insert(const int* __restrict__ coords, int n) {
    int i = blockIdx.x * blockDim.x + threadIdx.x;
    if (i >= n) return;
    int si = blockIdx.y;
    int shift = si + 1;
    int4 cd = reinterpret_cast<const int4*>(coords)[i];
    int vx = cd.x >> shift, vy = cd.y >> shift, vz = cd.z >> shift;
    uint32_t key = (uint32_t)((((cd.w * 512) + vx) * 512 + vy) * 512 + vz);
    uint32_t slot = hash32(key) & HMASK;
    int id = -1;
#pragma unroll 1
    while (true) {
        uint32_t old = atomicCAS(&g_keys[si][slot], EMPTYK, key);
        if (old == EMPTYK) {
            id = atomicAdd(&g_counter[si], 1);
            atomicExch(&g_vals[si][slot], id);
            break;
        }
        if (old == key) {
            volatile int* vp = (volatile int*)&g_vals[si][slot];
#pragma unroll 1
            while ((id = *vp) < 0) { __nanosleep(40); }
            break;
        }
        slot = (slot + 1) & HMASK;
    }
    g_pt2vox[si][i] = id;
    atomicAdd(&g_counts[si][id], 1);
}

// ---------------- K3: per-voxel feature sums (all 3 scales, one feats read) ----------------
__global__ void k_accum(const float* __restrict__ feats, int n) {
    int tid = blockIdx.x * blockDim.x + threadIdx.x;
    if (tid >= n * 16) return;
    int p = tid >> 4, q = tid & 15;
    float4 v = reinterpret_cast<const float4*>(feats)[tid];
#pragma unroll
    for (int si = 0; si < 3; si++) {
        int vid = g_pt2vox[si][p];
        float* dst = &g_sums[si][(size_t)vid * 64 + q * 4];
        asm volatile("red.global.add.v4.f32 [%0], {%1, %2, %3, %4};"
                     :: "l"(dst), "f"(v.x), "f"(v.y), "f"(v.z), "f"(v.w)
                     : "memory");
    }
}

// ---------------- K4: 8-corner probe + exact trilinear argmax ----------------
__device__ __forceinline__ int hlookup(int si, uint32_t key) {
    uint32_t slot = hash32(key) & HMASK;
#pragma unroll 1
    while (true) {
        uint32_t k = g_keys[si][slot];
        if (k == key) return g_vals[si][slot];
        if (k == EMPTYK) return -1;
        slot = (slot + 1) & HMASK;
    }
}

__global__ void k_select(const int* __restrict__ coords, int n) {
    int i = blockIdx.x * blockDim.x + threadIdx.x;
    if (i >= n) return;
    int si = blockIdx.y;
    int shift = si + 1;
    int4 cd = reinterpret_cast<const int4*>(coords)[i];
    int scale = 1 << shift;
    float invs = 1.0f / (float)scale;
    int vx = cd.x >> shift, vy = cd.y >> shift, vz = cd.z >> shift;
    float fx = (float)(cd.x - (vx << shift)) * invs;   // exact binary fractions
    float fy = (float)(cd.y - (vy << shift)) * invs;
    float fz = (float)(cd.z - (vz << shift)) * invs;
    float gx = 1.0f - fx, gy = 1.0f - fy, gz = 1.0f - fz;

    float bestw = -1.0f;
    int bestid = 0;
#pragma unroll
    for (int j = 0; j < 8; j++) {
        int bx = (j >> 2) & 1, by = (j >> 1) & 1, bz = j & 1;
        float w = (bx ? fx : gx) * (by ? fy : gy) * (bz ? fz : gz);  // exact
        uint32_t key = (uint32_t)((((cd.w * 512) + (vx + bx)) * 512 + (vy + by)) * 512 + (vz + bz));
        int id = hlookup(si, key);
        float val = (id >= 0) ? w : 0.0f;
        if (val > bestw) { bestw = val; bestid = id; }  // first-max == jnp.argmax
    }
    g_ptidx[si][i] = bestid;
}

// ---------------- K5: per-scale residual MLP (warp-independent) ----------------
// R5-winning structure (8 warps/CTA, warp-independent, 4 pts/iter), with:
//   - __launch_bounds__(256,3): 85-reg budget (no spill pressure)
//   - next-tile gather prefetched into registers behind GEMV1/GEMV2
#define WPK_ULL   (2 * 32 * 66)                    // 4224 ull = 33792 B
#define ACT_OFF_F (WPK_ULL * 2)                    // float index of act region
#define SMEM_MLP  (WPK_ULL * 8 + 8 * 512 * 4)     // 33792 + 16384 = 50176 B

__global__ __launch_bounds__(TPM, 3) void k_mlp(
    const float* __restrict__ feats,
    const float* __restrict__ W1g, const float* __restrict__ b1g,
    const float* __restrict__ W2g, const float* __restrict__ b2g,
    int n)
{
    extern __shared__ ull smu[];
    float* smf = (float*)smu;
    const int s    = blockIdx.y;
    const int bs   = blockIdx.x;
    const int nb   = gridDim.x;
    const int warp = threadIdx.x >> 5;
    const int lane = threadIdx.x & 31;
    const int c0   = lane * 2;

    // ---- stage + k-pair-pack this scale's weights ----
    for (int j = threadIdx.x; j < 8192; j += TPM) {
        int layer = j >> 12, r = j & 4095;
        int k = r >> 6, c = r & 63;
        float v = (layer ? W2g : W1g)[s * 4096 + r];
        smf[(((layer * 32 + (c >> 1)) * 66) + ((k >> 1) << 1) + (c & 1)) * 2 + (k & 1)] = v;
    }
    const float b1x = b1g[s * 64 + c0], b1y = b1g[s * 64 + c0 + 1];
    const float b2x = b2g[s * 64 + c0], b2y = b2g[s * 64 + c0 + 1];
    __syncthreads();

    const ull* w0b = smu + lane * 66;          // layer-1 weight row for this lane
    const ull* w1b = smu + 2112 + lane * 66;   // layer-2
    float* resw = smf + ACT_OFF_F + warp * 512;    // [4][64]
    float* hw   = resw + 256;                       // [4][64]

    const int tiles = (n + 3) >> 2;
    const int step  = nb * 8;

    float2 pf[4], up[4];

#define PREFETCH(I0, PF, UP) do {                                             \
    _Pragma("unroll")                                                         \
    for (int p = 0; p < 4; p++) {                                             \
        int i = (I0) + p; if (i >= n) i = n - 1;                              \
        int idx = g_ptidx[s][i];                                              \
        float inv = 1.0f / (float)g_counts[s][idx];                           \
        float2 sv = *(const float2*)&g_sums[s][(size_t)idx * 64 + c0];        \
        (UP)[p].x = sv.x * inv; (UP)[p].y = sv.y * inv;                       \
        (PF)[p] = *(const float2*)&feats[(size_t)i * 64 + c0];                \
    }                                                                         \
} while (0)

#define GEMV(SRCF, WB) do {                                                    \
    _Pragma("unroll") for (int p = 0; p < 4; p++) { a0[p] = 0ull; a1[p] = 0ull; } \
    _Pragma("unroll")                                                          \
    for (int kc = 0; kc < 16; kc++) {                                          \
        ulonglong2 wA = *(const ulonglong2*)&(WB)[4 * kc];                     \
        ulonglong2 wB_ = *(const ulonglong2*)&(WB)[4 * kc + 2];                \
        _Pragma("unroll")                                                      \
        for (int p = 0; p < 4; p++) {                                          \
            ulonglong2 av = *(const ulonglong2*)&((const ull*)(SRCF))[p * 32 + 2 * kc]; \
            a0[p] = fma2(av.x, wA.x, a0[p]);                                   \
            a1[p] = fma2(av.x, wA.y, a1[p]);                                   \
            a0[p] = fma2(av.y, wB_.x, a0[p]);                                  \
            a1[p] = fma2(av.y, wB_.y, a1[p]);                                  \
        }                                                                      \
    }                                                                          \
} while (0)

    int t = bs * 8 + warp;
    if (t < tiles) PREFETCH(t * 4, pf, up);

    for (; t < tiles; t += step) {
        const int i0 = t * 4;

        // ---- residual from prefetched registers ----
#pragma unroll
        for (int p = 0; p < 4; p++)
            *(float2*)&resw[p * 64 + c0] = make_float2(pf[p].x - up[p].x,
                                                       pf[p].y - up[p].y);
        __syncwarp();

        ull a0[4], a1[4];
        // ---- GEMV1: h = relu(res @ W1 + b1) * feats ----
        GEMV(resw, w0b);
#pragma unroll
        for (int p = 0; p < 4; p++) {
            float2 u0 = unpack2(a0[p]);
            float2 u1 = unpack2(a1[p]);
            float h0 = fmaxf(u0.x + u0.y + b1x, 0.0f) * pf[p].x;
            float h1 = fmaxf(u1.x + u1.y + b1y, 0.0f) * pf[p].y;
            *(float2*)&hw[p * 64 + c0] = make_float2(h0, h1);
        }
        __syncwarp();

        // ---- prefetch next tile's gather (hidden behind GEMV2) ----
        float2 pf2[4], up2[4];
        int tn = t + step;
        if (tn < tiles) PREFETCH(tn * 4, pf2, up2);

        // ---- GEMV2: ms = relu(h @ W2 + b2) ----
        GEMV(hw, w1b);
#pragma unroll
        for (int p = 0; p < 4; p++) {
            if (i0 + p < n) {
                float2 u0 = unpack2(a0[p]);
                float2 u1 = unpack2(a1[p]);
                float m0 = fmaxf(u0.x + u0.y + b2x, 0.0f);
                float m1 = fmaxf(u1.x + u1.y + b2y, 0.0f);
                *(float2*)&g_ms[s][(size_t)(i0 + p) * 64 + c0] = make_float2(m0, m1);
            }
        }
#pragma unroll
        for (int p = 0; p < 4; p++) { pf[p] = pf2[p]; up[p] = up2[p]; }
        __syncwarp();
    }
#undef GEMV
#undef PREFETCH
}

// ---------------- K6: attention + combine (streaming) ----------------
__global__ __launch_bounds__(256) void k_att(
    const float* __restrict__ Wag, const float* __restrict__ bag,
    float* __restrict__ out, int n)
{
    int warp = threadIdx.x >> 5, lane = threadIdx.x & 31;
    int i = blockIdx.x * 8 + warp;
    if (i >= n) return;
    int c0 = lane * 2;

    float2 m0 = *(const float2*)&g_ms[0][(size_t)i * 64 + c0];
    float2 m1 = *(const float2*)&g_ms[1][(size_t)i * 64 + c0];
    float2 m2 = *(const float2*)&g_ms[2][(size_t)i * 64 + c0];
    float ssx = m0.x + m1.x + m2.x;
    float ssy = m0.y + m1.y + m2.y;

    float2 wa0 = *(const float2*)&Wag[c0];
    float2 wa1 = *(const float2*)&Wag[64 + c0];
    float2 wa2 = *(const float2*)&Wag[128 + c0];
    float p0 = ssx * wa0.x + ssy * wa0.y;
    float p1 = ssx * wa1.x + ssy * wa1.y;
    float p2 = ssx * wa2.x + ssy * wa2.y;
#pragma unroll
    for (int off = 16; off; off >>= 1) {
        p0 += __shfl_xor_sync(0xffffffffu, p0, off);
        p1 += __shfl_xor_sync(0xffffffffu, p1, off);
        p2 += __shfl_xor_sync(0xffffffffu, p2, off);
    }
    float a0 = 1.0f / (1.0f + expf(-(p0 + bag[0])));
    float a1 = 1.0f / (1.0f + expf(-(p1 + bag[1])));
    float a2 = 1.0f / (1.0f + expf(-(p2 + bag[2])));

    float2 o;
    o.x = m0.x * a0 + m1.x * a1 + m2.x * a2;
    o.y = m0.y * a0 + m1.y * a1 + m2.y * a2;
    *(float2*)&out[(size_t)i * 64 + c0] = o;
}

// ---------------- host launcher ----------------
extern "C" void kernel_launch(void* const* d_in, const int* in_sizes, int n_in,
                              void* d_out, int out_size) {
    const float* feats = (const float*)d_in[0];
    const int*   coords = (const int*)d_in[1];
    const float* W1 = (const float*)d_in[2];
    const float* b1 = (const float*)d_in[3];
    const float* W2 = (const float*)d_in[4];
    const float* b2 = (const float*)d_in[5];
    const float* Wa = (const float*)d_in[6];
    const float* ba = (const float*)d_in[7];
    float* out = (float*)d_out;

    int n = in_sizes[1] / 4;   // coords is (N,4) int32
    if (n > NMAX) n = NMAX;

    k_clear<<<4096, 256>>>(n);
    dim3 gi((n + 255) / 256, 3);
    k_insert<<<gi, 256>>>(coords, n);
    k_accum<<<(n * 16 + 255) / 256, 256>>>(feats, n);
    k_select<<<gi, 256>>>(coords, n);

    int sms = 148;
    cudaDeviceGetAttribute(&sms, cudaDevAttrMultiProcessorCount, 0);
    cudaFuncSetAttribute(k_mlp, cudaFuncAttributeMaxDynamicSharedMemorySize, SMEM_MLP);
    dim3 gm(sms * 3, 3);   // 3 CTAs/SM resident (reg-limited), persistent
    k_mlp<<<gm, TPM, SMEM_MLP>>>(feats, W1, b1, W2, b2, n);

    k_att<<<(n + 7) / 8, 256>>>(Wa, ba, out, n);
}

// round 10
// speedup vs baseline: 1.6192x; 1.2818x over previous
#include <cuda_runtime.h>
#include <cstdint>

#define NMAX   500000
#define HBITS  21
#define HSIZE  (1u << HBITS)
#define HMASK  (HSIZE - 1u)
#define EMPTYK 0xFFFFFFFFu
#define SP     40          // smem point-stride (floats): bank = 8*c + p pattern

typedef unsigned long long ull;
typedef unsigned int uint;

// ---------------- device scratch ----------------
__device__ uint32_t g_keys[3][HSIZE];
__device__ int      g_vals[3][HSIZE];
__device__ int      g_counter[3];
__device__ int      g_pt2vox[3][NMAX];
__device__ float    g_sums[3][NMAX * 64];
__device__ int      g_counts[3][NMAX];
__device__ float    g_inv[3][NMAX];
__device__ int      g_ptidx[3][NMAX];
__device__ float    g_ms[3][NMAX * 64];

__device__ __forceinline__ uint32_t hash32(uint32_t x) {
    x ^= x >> 16; x *= 0x85ebca6bu;
    x ^= x >> 13; x *= 0xc2b2ae35u;
    x ^= x >> 16;
    return x;
}

__device__ __forceinline__ uint f2tf(float v) {
    uint r;
    asm("cvt.rna.tf32.f32 %0, %1;" : "=r"(r) : "f"(v));
    return r;
}

// D += A(tf32) * B(tf32), m16n8k8, A row-major, B col-major, fp32 accum
__device__ __forceinline__ void mma_tf32(float4& d, const uint* a, uint b0, uint b1) {
    asm("mma.sync.aligned.m16n8k8.row.col.f32.tf32.tf32.f32 "
        "{%0,%1,%2,%3}, {%4,%5,%6,%7}, {%8,%9}, {%0,%1,%2,%3};"
        : "+f"(d.x), "+f"(d.y), "+f"(d.z), "+f"(d.w)
        : "r"(a[0]), "r"(a[1]), "r"(a[2]), "r"(a[3]), "r"(b0), "r"(b1));
}

// ---------------- K1: clear all 3 hash tables + sums/counts ----------------
__global__ void k_clear(int n) {
    int tid = blockIdx.x * blockDim.x + threadIdx.x;
    int stride = gridDim.x * blockDim.x;
    int m4 = n * 16;
    float4 z = make_float4(0.f, 0.f, 0.f, 0.f);
#pragma unroll
    for (int s = 0; s < 3; s++) {
        float4* s4 = reinterpret_cast<float4*>(&g_sums[s][0]);
        for (int i = tid; i < m4; i += stride) s4[i] = z;
    }
    for (int i = tid; i < (int)HSIZE; i += stride) {
        g_keys[0][i] = EMPTYK; g_keys[1][i] = EMPTYK; g_keys[2][i] = EMPTYK;
        g_vals[0][i] = -1;     g_vals[1][i] = -1;     g_vals[2][i] = -1;
    }
    for (int i = tid; i < n; i += stride) {
        g_counts[0][i] = 0; g_counts[1][i] = 0; g_counts[2][i] = 0;
    }
    if (tid == 0) { g_counter[0] = 0; g_counter[1] = 0; g_counter[2] = 0; }
}

// ---------------- K2: hash-insert (all scales via blockIdx.y) ----------------
__global__ void k_insert(const int* __restrict__ coords, int n) {
    int i = blockIdx.x * blockDim.x + threadIdx.x;
    if (i >= n) return;
    int si = blockIdx.y;
    int shift = si + 1;
    int4 cd = reinterpret_cast<const int4*>(coords)[i];
    int vx = cd.x >> shift, vy = cd.y >> shift, vz = cd.z >> shift;
    uint32_t key = (uint32_t)((((cd.w * 512) + vx) * 512 + vy) * 512 + vz);
    uint32_t slot = hash32(key) & HMASK;
    int id = -1;
#pragma unroll 1
    while (true) {
        uint32_t old = atomicCAS(&g_keys[si][slot], EMPTYK, key);
        if (old == EMPTYK) {
            id = atomicAdd(&g_counter[si], 1);
            atomicExch(&g_vals[si][slot], id);
            break;
        }
        if (old == key) {
            volatile int* vp = (volatile int*)&g_vals[si][slot];
#pragma unroll 1
            while ((id = *vp) < 0) { __nanosleep(40); }
            break;
        }
        slot = (slot + 1) & HMASK;
    }
    g_pt2vox[si][i] = id;
    atomicAdd(&g_counts[si][id], 1);
}

// ---------------- K2b: per-voxel reciprocal counts (exact 1.0f/count) ----------------
__global__ void k_inv(int n) {
    int i = blockIdx.x * blockDim.x + threadIdx.x;
    if (i >= n) return;
#pragma unroll
    for (int s = 0; s < 3; s++)
        if (i < g_counter[s]) g_inv[s][i] = 1.0f / (float)g_counts[s][i];
}

// ---------------- K3: per-voxel feature sums (all 3 scales, one feats read) ----------------
__global__ void k_accum(const float* __restrict__ feats, int n) {
    int tid = blockIdx.x * blockDim.x + threadIdx.x;
    if (tid >= n * 16) return;
    int p = tid >> 4, q = tid & 15;
    float4 v = reinterpret_cast<const float4*>(feats)[tid];
#pragma unroll
    for (int si = 0; si < 3; si++) {
        int vid = g_pt2vox[si][p];
        float* dst = &g_sums[si][(size_t)vid * 64 + q * 4];
        asm volatile("red.global.add.v4.f32 [%0], {%1, %2, %3, %4};"
                     :: "l"(dst), "f"(v.x), "f"(v.y), "f"(v.z), "f"(v.w)
                     : "memory");
    }
}

// ---------------- K4: 8-corner probe + exact trilinear argmax ----------------
__device__ __forceinline__ int hlookup(int si, uint32_t key) {
    uint32_t slot = hash32(key) & HMASK;
#pragma unroll 1
    while (true) {
        uint32_t k = g_keys[si][slot];
        if (k == key) return g_vals[si][slot];
        if (k == EMPTYK) return -1;
        slot = (slot + 1) & HMASK;
    }
}

__global__ void k_select(const int* __restrict__ coords, int n) {
    int i = blockIdx.x * blockDim.x + threadIdx.x;
    if (i >= n) return;
    int si = blockIdx.y;
    int shift = si + 1;
    int4 cd = reinterpret_cast<const int4*>(coords)[i];
    int scale = 1 << shift;
    float invs = 1.0f / (float)scale;
    int vx = cd.x >> shift, vy = cd.y >> shift, vz = cd.z >> shift;
    float fx = (float)(cd.x - (vx << shift)) * invs;   // exact binary fractions
    float fy = (float)(cd.y - (vy << shift)) * invs;
    float fz = (float)(cd.z - (vz << shift)) * invs;
    float gx = 1.0f - fx, gy = 1.0f - fy, gz = 1.0f - fz;

    float bestw = -1.0f;
    int bestid = 0;
#pragma unroll
    for (int j = 0; j < 8; j++) {
        int bx = (j >> 2) & 1, by = (j >> 1) & 1, bz = j & 1;
        float w = (bx ? fx : gx) * (by ? fy : gy) * (bz ? fz : gz);  // exact
        uint32_t key = (uint32_t)((((cd.w * 512) + (vx + bx)) * 512 + (vy + by)) * 512 + (vz + bz));
        int id = hlookup(si, key);
        float val = (id >= 0) ? w : 0.0f;
        if (val > bestw) { bestw = val; bestid = id; }  // first-max == jnp.argmax
    }
    g_ptidx[si][i] = bestid;
}

// ---------------- K5: per-scale residual MLP via tf32 tensor MMA ----------------
// CTA = 128 thr = 4 warps; warp w owns output channels [16w, 16w+16).
// Weights live in registers as A-fragments (loaded once, tf32).
// Activations transposed [chan][pt] in smem, stride SP=40 -> B-frag LDS
// conflict-free (bank = 8*tg + gr). 16 points per tile, persistent CTAs.
__global__ __launch_bounds__(128, 5) void k_mlp(
    const float* __restrict__ feats,
    const float* __restrict__ W1g, const float* __restrict__ b1g,
    const float* __restrict__ W2g, const float* __restrict__ b2g,
    int n)
{
    __shared__ float resT[64 * SP];
    __shared__ float fT[64 * SP];
    __shared__ float hT[64 * SP];

    const int s  = blockIdx.y;
    const int w  = threadIdx.x >> 5;
    const int l  = threadIdx.x & 31;
    const int gr = l >> 2;     // group row 0..7
    const int tg = l & 3;      // thread-in-group 0..3

    // ---- load weight A-fragments (tf32) once ----
    // A[m,k] = W[k][m]; a0:(gr,tg) a1:(gr+8,tg) a2:(gr,tg+4) a3:(gr+8,tg+4)
    uint a1f[8][4], a2f[8][4];
    const int m0 = 16 * w + gr;
#pragma unroll
    for (int kt = 0; kt < 8; kt++) {
        int kb = 8 * kt;
        a1f[kt][0] = f2tf(W1g[s * 4096 + (kb + tg) * 64 + m0]);
        a1f[kt][1] = f2tf(W1g[s * 4096 + (kb + tg) * 64 + m0 + 8]);
        a1f[kt][2] = f2tf(W1g[s * 4096 + (kb + tg + 4) * 64 + m0]);
        a1f[kt][3] = f2tf(W1g[s * 4096 + (kb + tg + 4) * 64 + m0 + 8]);
        a2f[kt][0] = f2tf(W2g[s * 4096 + (kb + tg) * 64 + m0]);
        a2f[kt][1] = f2tf(W2g[s * 4096 + (kb + tg) * 64 + m0 + 8]);
        a2f[kt][2] = f2tf(W2g[s * 4096 + (kb + tg + 4) * 64 + m0]);
        a2f[kt][3] = f2tf(W2g[s * 4096 + (kb + tg + 4) * 64 + m0 + 8]);
    }
    const float b1lo = b1g[s * 64 + m0], b1hi = b1g[s * 64 + m0 + 8];
    const float b2lo = b2g[s * 64 + m0], b2hi = b2g[s * 64 + m0 + 8];

    const int tiles = (n + 15) >> 4;

    for (int t = blockIdx.x; t < tiles; t += gridDim.x) {
        const int i0 = t * 16;

        // ---- gather + transpose: res and feats into [chan][pt] smem ----
        {
            int p  = threadIdx.x & 15;
            int cg = threadIdx.x >> 4;           // channel group 0..7
            int i = i0 + p; if (i >= n) i = n - 1;
            int idx = g_ptidx[s][i];
            float inv = g_inv[s][idx];
            const float4* fr = (const float4*)&feats[(size_t)i * 64 + cg * 8];
            const float4* sr = (const float4*)&g_sums[s][(size_t)idx * 64 + cg * 8];
            float4 f0 = fr[0], f1 = fr[1];
            float4 s0 = sr[0], s1 = sr[1];
            float fv[8] = {f0.x, f0.y, f0.z, f0.w, f1.x, f1.y, f1.z, f1.w};
            float sv[8] = {s0.x, s0.y, s0.z, s0.w, s1.x, s1.y, s1.z, s1.w};
#pragma unroll
            for (int j = 0; j < 8; j++) {
                int c = cg * 8 + j;
                fT[c * SP + p]   = fv[j];
                resT[c * SP + p] = fv[j] - sv[j] * inv;
            }
        }
        __syncthreads();

        // ---- layer 1: h = relu(W1^T @ res + b1) * feats ----
#pragma unroll
        for (int nt = 0; nt < 2; nt++) {
            float4 C = make_float4(0.f, 0.f, 0.f, 0.f);
            const int col = gr + nt * 8;
#pragma unroll
            for (int kt = 0; kt < 8; kt++) {
                uint b0 = f2tf(resT[(tg + kt * 8) * SP + col]);
                uint b1 = f2tf(resT[(tg + 4 + kt * 8) * SP + col]);
                mma_tf32(C, a1f[kt], b0, b1);
            }
            // C layout: c0,c1 -> (m0, 2tg(+1)); c2,c3 -> (m0+8, 2tg(+1)), cols +8nt
            int pc = 2 * tg + nt * 8;
            float2 flo = *(const float2*)&fT[m0 * SP + pc];
            float2 fhi = *(const float2*)&fT[(m0 + 8) * SP + pc];
            float2 hlo, hhi;
            hlo.x = fmaxf(C.x + b1lo, 0.f) * flo.x;
            hlo.y = fmaxf(C.y + b1lo, 0.f) * flo.y;
            hhi.x = fmaxf(C.z + b1hi, 0.f) * fhi.x;
            hhi.y = fmaxf(C.w + b1hi, 0.f) * fhi.y;
            *(float2*)&hT[m0 * SP + pc] = hlo;
            *(float2*)&hT[(m0 + 8) * SP + pc] = hhi;
        }
        __syncthreads();

        // ---- layer 2: ms = relu(W2^T @ h + b2) -> g_ms ----
#pragma unroll
        for (int nt = 0; nt < 2; nt++) {
            float4 C = make_float4(0.f, 0.f, 0.f, 0.f);
            const int col = gr + nt * 8;
#pragma unroll
            for (int kt = 0; kt < 8; kt++) {
                uint b0 = f2tf(hT[(tg + kt * 8) * SP + col]);
                uint b1 = f2tf(hT[(tg + 4 + kt * 8) * SP + col]);
                mma_tf32(C, a2f[kt], b0, b1);
            }
            int p0 = i0 + 2 * tg + nt * 8;
            if (p0 < n) {
                g_ms[s][(size_t)p0 * 64 + m0]     = fmaxf(C.x + b2lo, 0.f);
                g_ms[s][(size_t)p0 * 64 + m0 + 8] = fmaxf(C.z + b2hi, 0.f);
            }
            if (p0 + 1 < n) {
                g_ms[s][(size_t)(p0 + 1) * 64 + m0]     = fmaxf(C.y + b2lo, 0.f);
                g_ms[s][(size_t)(p0 + 1) * 64 + m0 + 8] = fmaxf(C.w + b2hi, 0.f);
            }
        }
        __syncthreads();   // protect resT/fT/hT WAR for next tile
    }
}

// ---------------- K6: attention + combine (streaming) ----------------
__global__ __launch_bounds__(256) void k_att(
    const float* __restrict__ Wag, const float* __restrict__ bag,
    float* __restrict__ out, int n)
{
    int warp = threadIdx.x >> 5, lane = threadIdx.x & 31;
    int i = blockIdx.x * 8 + warp;
    if (i >= n) return;
    int c0 = lane * 2;

    float2 m0 = *(const float2*)&g_ms[0][(size_t)i * 64 + c0];
    float2 m1 = *(const float2*)&g_ms[1][(size_t)i * 64 + c0];
    float2 m2 = *(const float2*)&g_ms[2][(size_t)i * 64 + c0];
    float ssx = m0.x + m1.x + m2.x;
    float ssy = m0.y + m1.y + m2.y;

    float2 wa0 = *(const float2*)&Wag[c0];
    float2 wa1 = *(const float2*)&Wag[64 + c0];
    float2 wa2 = *(const float2*)&Wag[128 + c0];
    float p0 = ssx * wa0.x + ssy * wa0.y;
    float p1 = ssx * wa1.x + ssy * wa1.y;
    float p2 = ssx * wa2.x + ssy * wa2.y;
#pragma unroll
    for (int off = 16; off; off >>= 1) {
        p0 += __shfl_xor_sync(0xffffffffu, p0, off);
        p1 += __shfl_xor_sync(0xffffffffu, p1, off);
        p2 += __shfl_xor_sync(0xffffffffu, p2, off);
    }
    float a0 = 1.0f / (1.0f + expf(-(p0 + bag[0])));
    float a1 = 1.0f / (1.0f + expf(-(p1 + bag[1])));
    float a2 = 1.0f / (1.0f + expf(-(p2 + bag[2])));

    float2 o;
    o.x = m0.x * a0 + m1.x * a1 + m2.x * a2;
    o.y = m0.y * a0 + m1.y * a1 + m2.y * a2;
    *(float2*)&out[(size_t)i * 64 + c0] = o;
}

// ---------------- host launcher ----------------
extern "C" void kernel_launch(void* const* d_in, const int* in_sizes, int n_in,
                              void* d_out, int out_size) {
    const float* feats = (const float*)d_in[0];
    const int*   coords = (const int*)d_in[1];
    const float* W1 = (const float*)d_in[2];
    const float* b1 = (const float*)d_in[3];
    const float* W2 = (const float*)d_in[4];
    const float* b2 = (const float*)d_in[5];
    const float* Wa = (const float*)d_in[6];
    const float* ba = (const float*)d_in[7];
    float* out = (float*)d_out;

    int n = in_sizes[1] / 4;   // coords is (N,4) int32
    if (n > NMAX) n = NMAX;

    k_clear<<<4096, 256>>>(n);
    dim3 gi((n + 255) / 256, 3);
    k_insert<<<gi, 256>>>(coords, n);
    k_inv<<<(n + 255) / 256, 256>>>(n);
    k_accum<<<(n * 16 + 255) / 256, 256>>>(feats, n);
    k_select<<<gi, 256>>>(coords, n);

    int sms = 148;
    cudaDeviceGetAttribute(&sms, cudaDevAttrMultiProcessorCount, 0);
    dim3 gm(sms * 5, 3);   // 5 CTAs/SM resident, persistent over tiles
    k_mlp<<<gm, 128>>>(feats, W1, b1, W2, b2, n);

    k_att<<<(n + 7) / 8, 256>>>(Wa, ba, out, n);
}

// round 11
// speedup vs baseline: 1.9258x; 1.1894x over previous
#include <cuda_runtime.h>
#include <cstdint>

#define NMAX   500000
#define HBITS  21
#define HSIZE  (1u << HBITS)
#define HMASK  (HSIZE - 1u)
#define EMPTYK 0xFFFFFFFFu
#define SP     40          // smem point-stride (floats): 32 points + 8 pad

typedef unsigned long long ull;
typedef unsigned int uint;

// ---------------- device scratch ----------------
__device__ uint32_t g_keys[3][HSIZE];
__device__ int      g_vals[3][HSIZE];
__device__ int      g_counter[3];
__device__ int      g_pt2vox[3][NMAX];
__device__ float    g_sums[3][NMAX * 64];
__device__ int      g_counts[3][NMAX];
__device__ float    g_inv[3][NMAX];
__device__ int      g_ptidx[3][NMAX];
__device__ float    g_ms[3][NMAX * 64];

__device__ __forceinline__ uint32_t hash32(uint32_t x) {
    x ^= x >> 16; x *= 0x85ebca6bu;
    x ^= x >> 13; x *= 0xc2b2ae35u;
    x ^= x >> 16;
    return x;
}

__device__ __forceinline__ uint f2tf(float v) {
    uint r;
    asm("cvt.rna.tf32.f32 %0, %1;" : "=r"(r) : "f"(v));
    return r;
}

// D += A(tf32) * B(tf32), m16n8k8, A row-major, B col-major, fp32 accum
__device__ __forceinline__ void mma_tf32(float4& d, const uint* a, uint b0, uint b1) {
    asm("mma.sync.aligned.m16n8k8.row.col.f32.tf32.tf32.f32 "
        "{%0,%1,%2,%3}, {%4,%5,%6,%7}, {%8,%9}, {%0,%1,%2,%3};"
        : "+f"(d.x), "+f"(d.y), "+f"(d.z), "+f"(d.w)
        : "r"(a[0]), "r"(a[1]), "r"(a[2]), "r"(a[3]), "r"(b0), "r"(b1));
}

// ---------------- K1: clear hash tables + counts (sums cleared by prefix later) ----------------
__global__ void k_clear(int n) {
    int tid = blockIdx.x * blockDim.x + threadIdx.x;
    int stride = gridDim.x * blockDim.x;
    for (int i = tid; i < (int)HSIZE; i += stride) {
        g_keys[0][i] = EMPTYK; g_keys[1][i] = EMPTYK; g_keys[2][i] = EMPTYK;
        g_vals[0][i] = -1;     g_vals[1][i] = -1;     g_vals[2][i] = -1;
    }
    for (int i = tid; i < n; i += stride) {
        g_counts[0][i] = 0; g_counts[1][i] = 0; g_counts[2][i] = 0;
    }
    if (tid == 0) { g_counter[0] = 0; g_counter[1] = 0; g_counter[2] = 0; }
}

// ---------------- K2: hash-insert (all scales via blockIdx.y) ----------------
__global__ void k_insert(const int* __restrict__ coords, int n) {
    int i = blockIdx.x * blockDim.x + threadIdx.x;
    if (i >= n) return;
    int si = blockIdx.y;
    int shift = si + 1;
    int4 cd = reinterpret_cast<const int4*>(coords)[i];
    int vx = cd.x >> shift, vy = cd.y >> shift, vz = cd.z >> shift;
    uint32_t key = (uint32_t)((((cd.w * 512) + vx) * 512 + vy) * 512 + vz);
    uint32_t slot = hash32(key) & HMASK;
    int id = -1;
#pragma unroll 1
    while (true) {
        uint32_t old = atomicCAS(&g_keys[si][slot], EMPTYK, key);
        if (old == EMPTYK) {
            id = atomicAdd(&g_counter[si], 1);
            atomicExch(&g_vals[si][slot], id);
            break;
        }
        if (old == key) {
            volatile int* vp = (volatile int*)&g_vals[si][slot];
#pragma unroll 1
            while ((id = *vp) < 0) { __nanosleep(40); }
            break;
        }
        slot = (slot + 1) & HMASK;
    }
    g_pt2vox[si][i] = id;
    atomicAdd(&g_counts[si][id], 1);
}

// ---------------- K2b: zero live prefix of sums + per-voxel 1/count ----------------
__global__ void k_post() {
    int tid = blockIdx.x * blockDim.x + threadIdx.x;
    int stride = gridDim.x * blockDim.x;
    float4 z = make_float4(0.f, 0.f, 0.f, 0.f);
#pragma unroll
    for (int s = 0; s < 3; s++) {
        int nv = g_counter[s];
        float4* s4 = reinterpret_cast<float4*>(&g_sums[s][0]);
        int m4 = nv * 16;
        for (int i = tid; i < m4; i += stride) s4[i] = z;
        for (int i = tid; i < nv; i += stride)
            g_inv[s][i] = 1.0f / (float)g_counts[s][i];
    }
}

// ---------------- K3: per-voxel feature sums (all 3 scales, one feats read) ----------------
__global__ void k_accum(const float* __restrict__ feats, int n) {
    int tid = blockIdx.x * blockDim.x + threadIdx.x;
    if (tid >= n * 16) return;
    int p = tid >> 4, q = tid & 15;
    float4 v = reinterpret_cast<const float4*>(feats)[tid];
#pragma unroll
    for (int si = 0; si < 3; si++) {
        int vid = g_pt2vox[si][p];
        float* dst = &g_sums[si][(size_t)vid * 64 + q * 4];
        asm volatile("red.global.add.v4.f32 [%0], {%1, %2, %3, %4};"
                     :: "l"(dst), "f"(v.x), "f"(v.y), "f"(v.z), "f"(v.w)
                     : "memory");
    }
}

// ---------------- K4: 8-corner probe + exact trilinear argmax ----------------
__device__ __forceinline__ int hlookup(int si, uint32_t key) {
    uint32_t slot = hash32(key) & HMASK;
#pragma unroll 1
    while (true) {
        uint32_t k = g_keys[si][slot];
        if (k == key) return g_vals[si][slot];
        if (k == EMPTYK) return -1;
        slot = (slot + 1) & HMASK;
    }
}

__global__ void k_select(const int* __restrict__ coords, int n) {
    int i = blockIdx.x * blockDim.x + threadIdx.x;
    if (i >= n) return;
    int si = blockIdx.y;
    int shift = si + 1;
    int4 cd = reinterpret_cast<const int4*>(coords)[i];
    int scale = 1 << shift;
    float invs = 1.0f / (float)scale;
    int vx = cd.x >> shift, vy = cd.y >> shift, vz = cd.z >> shift;
    float fx = (float)(cd.x - (vx << shift)) * invs;   // exact binary fractions
    float fy = (float)(cd.y - (vy << shift)) * invs;
    float fz = (float)(cd.z - (vz << shift)) * invs;
    float gx = 1.0f - fx, gy = 1.0f - fy, gz = 1.0f - fz;

    float bestw = -1.0f;
    int bestid = 0;
#pragma unroll
    for (int j = 0; j < 8; j++) {
        int bx = (j >> 2) & 1, by = (j >> 1) & 1, bz = j & 1;
        float w = (bx ? fx : gx) * (by ? fy : gy) * (bz ? fz : gz);  // exact
        uint32_t key = (uint32_t)((((cd.w * 512) + (vx + bx)) * 512 + (vy + by)) * 512 + (vz + bz));
        int id = hlookup(si, key);
        float val = (id >= 0) ? w : 0.0f;
        if (val > bestw) { bestw = val; bestid = id; }  // first-max == jnp.argmax
    }
    g_ptidx[si][i] = bestid;
}

// ---------------- K5: per-scale residual MLP via tf32 tensor MMA (32-pt tiles) ----------------
// CTA = 128 thr = 4 warps; warp w owns output channels [16w, 16w+16).
// Weights live in registers as A-fragments (loaded once, tf32).
// Activations transposed [chan][pt] in smem, stride SP=40 (32 pts + 8 pad),
// conflict-free B-frag LDS. 32 points per tile, persistent CTAs.
__global__ __launch_bounds__(128, 5) void k_mlp(
    const float* __restrict__ feats,
    const float* __restrict__ W1g, const float* __restrict__ b1g,
    const float* __restrict__ W2g, const float* __restrict__ b2g,
    int n)
{
    __shared__ float resT[64 * SP];
    __shared__ float fT[64 * SP];
    __shared__ float hT[64 * SP];

    const int s  = blockIdx.y;
    const int w  = threadIdx.x >> 5;
    const int l  = threadIdx.x & 31;
    const int gr = l >> 2;     // group row 0..7
    const int tg = l & 3;      // thread-in-group 0..3

    // ---- load weight A-fragments (tf32) once ----
    uint a1f[8][4], a2f[8][4];
    const int m0 = 16 * w + gr;
#pragma unroll
    for (int kt = 0; kt < 8; kt++) {
        int kb = 8 * kt;
        a1f[kt][0] = f2tf(W1g[s * 4096 + (kb + tg) * 64 + m0]);
        a1f[kt][1] = f2tf(W1g[s * 4096 + (kb + tg) * 64 + m0 + 8]);
        a1f[kt][2] = f2tf(W1g[s * 4096 + (kb + tg + 4) * 64 + m0]);
        a1f[kt][3] = f2tf(W1g[s * 4096 + (kb + tg + 4) * 64 + m0 + 8]);
        a2f[kt][0] = f2tf(W2g[s * 4096 + (kb + tg) * 64 + m0]);
        a2f[kt][1] = f2tf(W2g[s * 4096 + (kb + tg) * 64 + m0 + 8]);
        a2f[kt][2] = f2tf(W2g[s * 4096 + (kb + tg + 4) * 64 + m0]);
        a2f[kt][3] = f2tf(W2g[s * 4096 + (kb + tg + 4) * 64 + m0 + 8]);
    }
    const float b1lo = b1g[s * 64 + m0], b1hi = b1g[s * 64 + m0 + 8];
    const float b2lo = b2g[s * 64 + m0], b2hi = b2g[s * 64 + m0 + 8];

    const int tiles = (n + 31) >> 5;

    for (int t = blockIdx.x; t < tiles; t += gridDim.x) {
        const int i0 = t * 32;

        // ---- gather + transpose: res and feats into [chan][pt] smem ----
        // thread -> point p = tid&31, channel group cg = tid>>5 (16 chans each)
        {
            int p  = threadIdx.x & 31;
            int cg = threadIdx.x >> 5;           // 0..3
            int i = i0 + p; if (i >= n) i = n - 1;
            int idx = g_ptidx[s][i];
            float inv = g_inv[s][idx];
            const float4* fr = (const float4*)&feats[(size_t)i * 64 + cg * 16];
            const float4* sr = (const float4*)&g_sums[s][(size_t)idx * 64 + cg * 16];
#pragma unroll
            for (int q = 0; q < 4; q++) {
                float4 f = fr[q];
                float4 sv = sr[q];
                int c = cg * 16 + q * 4;
                fT[(c + 0) * SP + p] = f.x;  resT[(c + 0) * SP + p] = f.x - sv.x * inv;
                fT[(c + 1) * SP + p] = f.y;  resT[(c + 1) * SP + p] = f.y - sv.y * inv;
                fT[(c + 2) * SP + p] = f.z;  resT[(c + 2) * SP + p] = f.z - sv.z * inv;
                fT[(c + 3) * SP + p] = f.w;  resT[(c + 3) * SP + p] = f.w - sv.w * inv;
            }
        }
        __syncthreads();

        // ---- layer 1: h = relu(W1^T @ res + b1) * feats ----
#pragma unroll
        for (int nt = 0; nt < 4; nt++) {
            float4 C = make_float4(0.f, 0.f, 0.f, 0.f);
            const int col = gr + nt * 8;
#pragma unroll
            for (int kt = 0; kt < 8; kt++) {
                uint b0 = f2tf(resT[(tg + kt * 8) * SP + col]);
                uint b1 = f2tf(resT[(tg + 4 + kt * 8) * SP + col]);
                mma_tf32(C, a1f[kt], b0, b1);
            }
            int pc = 2 * tg + nt * 8;
            float2 flo = *(const float2*)&fT[m0 * SP + pc];
            float2 fhi = *(const float2*)&fT[(m0 + 8) * SP + pc];
            float2 hlo, hhi;
            hlo.x = fmaxf(C.x + b1lo, 0.f) * flo.x;
            hlo.y = fmaxf(C.y + b1lo, 0.f) * flo.y;
            hhi.x = fmaxf(C.z + b1hi, 0.f) * fhi.x;
            hhi.y = fmaxf(C.w + b1hi, 0.f) * fhi.y;
            *(float2*)&hT[m0 * SP + pc] = hlo;
            *(float2*)&hT[(m0 + 8) * SP + pc] = hhi;
        }
        __syncthreads();

        // ---- layer 2: ms = relu(W2^T @ h + b2) -> g_ms ----
#pragma unroll
        for (int nt = 0; nt < 4; nt++) {
            float4 C = make_float4(0.f, 0.f, 0.f, 0.f);
            const int col = gr + nt * 8;
#pragma unroll
            for (int kt = 0; kt < 8; kt++) {
                uint b0 = f2tf(hT[(tg + kt * 8) * SP + col]);
                uint b1 = f2tf(hT[(tg + 4 + kt * 8) * SP + col]);
                mma_tf32(C, a2f[kt], b0, b1);
            }
            int p0 = i0 + 2 * tg + nt * 8;
            if (p0 < n) {
                g_ms[s][(size_t)p0 * 64 + m0]     = fmaxf(C.x + b2lo, 0.f);
                g_ms[s][(size_t)p0 * 64 + m0 + 8] = fmaxf(C.z + b2hi, 0.f);
            }
            if (p0 + 1 < n) {
                g_ms[s][(size_t)(p0 + 1) * 64 + m0]     = fmaxf(C.y + b2lo, 0.f);
                g_ms[s][(size_t)(p0 + 1) * 64 + m0 + 8] = fmaxf(C.w + b2hi, 0.f);
            }
        }
        __syncthreads();   // protect resT/fT/hT WAR for next tile
    }
}

// ---------------- K6: attention + combine (streaming) ----------------
__global__ __launch_bounds__(256) void k_att(
    const float* __restrict__ Wag, const float* __restrict__ bag,
    float* __restrict__ out, int n)
{
    int warp = threadIdx.x >> 5, lane = threadIdx.x & 31;
    int i = blockIdx.x * 8 + warp;
    if (i >= n) return;
    int c0 = lane * 2;

    float2 m0 = *(const float2*)&g_ms[0][(size_t)i * 64 + c0];
    float2 m1 = *(const float2*)&g_ms[1][(size_t)i * 64 + c0];
    float2 m2 = *(const float2*)&g_ms[2][(size_t)i * 64 + c0];
    float ssx = m0.x + m1.x + m2.x;
    float ssy = m0.y + m1.y + m2.y;

    float2 wa0 = *(const float2*)&Wag[c0];
    float2 wa1 = *(const float2*)&Wag[64 + c0];
    float2 wa2 = *(const float2*)&Wag[128 + c0];
    float p0 = ssx * wa0.x + ssy * wa0.y;
    float p1 = ssx * wa1.x + ssy * wa1.y;
    float p2 = ssx * wa2.x + ssy * wa2.y;
#pragma unroll
    for (int off = 16; off; off >>= 1) {
        p0 += __shfl_xor_sync(0xffffffffu, p0, off);
        p1 += __shfl_xor_sync(0xffffffffu, p1, off);
        p2 += __shfl_xor_sync(0xffffffffu, p2, off);
    }
    float a0 = 1.0f / (1.0f + expf(-(p0 + bag[0])));
    float a1 = 1.0f / (1.0f + expf(-(p1 + bag[1])));
    float a2 = 1.0f / (1.0f + expf(-(p2 + bag[2])));

    float2 o;
    o.x = m0.x * a0 + m1.x * a1 + m2.x * a2;
    o.y = m0.y * a0 + m1.y * a1 + m2.y * a2;
    *(float2*)&out[(size_t)i * 64 + c0] = o;
}

// ---------------- host launcher ----------------
extern "C" void kernel_launch(void* const* d_in, const int* in_sizes, int n_in,
                              void* d_out, int out_size) {
    const float* feats = (const float*)d_in[0];
    const int*   coords = (const int*)d_in[1];
    const float* W1 = (const float*)d_in[2];
    const float* b1 = (const float*)d_in[3];
    const float* W2 = (const float*)d_in[4];
    const float* b2 = (const float*)d_in[5];
    const float* Wa = (const float*)d_in[6];
    const float* ba = (const float*)d_in[7];
    float* out = (float*)d_out;

    int n = in_sizes[1] / 4;   // coords is (N,4) int32
    if (n > NMAX) n = NMAX;

    k_clear<<<2048, 256>>>(n);
    dim3 gi((n + 255) / 256, 3);
    k_insert<<<gi, 256>>>(coords, n);
    k_post<<<2048, 256>>>();
    k_accum<<<(n * 16 + 255) / 256, 256>>>(feats, n);
    k_select<<<gi, 256>>>(coords, n);

    int sms = 148;
    cudaDeviceGetAttribute(&sms, cudaDevAttrMultiProcessorCount, 0);
    dim3 gm(sms * 5, 3);   // 5 CTAs/SM resident, persistent over tiles
    k_mlp<<<gm, 128>>>(feats, W1, b1, W2, b2, n);

    k_att<<<(n + 7) / 8, 256>>>(Wa, ba, out, n);
}